// round 12
// baseline (speedup 1.0000x reference)
#include <cuda_runtime.h>
#include <cuda_fp16.h>
#include <stdint.h>

// ---------------------------------------------------------------------------
// StyleGAN2 modulated 3x3 conv, NHWC, N=16 H=W=64 C=O=512
// Round 12: single-product fp16 mma.sync. CTA 256Mx128N, 512 threads,
//           warp tile 32x64. Tap-PAIR groups (2 taps per barrier) to
//           amortize per-sync bubble; A halo 6x66 double-buffered;
//           B 4-slot ring (global tile index & 3). 1 CTA/SM, 16 warps.
// ---------------------------------------------------------------------------

#define NN 16
#define HH 64
#define WW 64
#define CC 512
#define OO 512
#define NWD 14

#define A_BYTES 50688        // 396 halo rows (6x66) x 128B, kc=64
#define OFF_B0  101376       // after 2 A buffers
#define B_BYTES 16384        // 128 o-rows x 128B
#define SMEM_TOTAL (OFF_B0 + 4 * B_BYTES)   // 166912

// ---- device scratch (allocation-free) --------------------------------------
__device__ float g_s[NN * CC];
__device__ float g_dmul[NN * OO];
__device__ float g_ssq[CC * OO];
__device__ __half g_xh[NN * HH * WW * CC];   // fp16(x*s)
__device__ __half g_wt[9 * OO * CC];         // fp16 w^T [tap][o][c]

// ---- helpers -----------------------------------------------------------------
static __device__ __forceinline__ uint32_t smem_u32(const void* p) {
    uint32_t a;
    asm("{ .reg .u64 t; cvta.to.shared.u64 t, %1; cvt.u32.u64 %0, t; }"
        : "=r"(a) : "l"(p));
    return a;
}

#define CP16(dst, src, sz)                                                   \
    asm volatile("cp.async.cg.shared.global [%0], [%1], 16, %2;"             \
                 :: "r"(dst), "l"(src), "r"(sz) : "memory")
#define CP_COMMIT() asm volatile("cp.async.commit_group;" ::: "memory")
#define CP_WAIT0()  asm volatile("cp.async.wait_group 0;" ::: "memory")

#define LDSM4(r, addr)                                                       \
    asm volatile("ldmatrix.sync.aligned.m8n8.x4.shared.b16 "                 \
                 "{%0,%1,%2,%3}, [%4];"                                      \
                 : "=r"((r)[0]), "=r"((r)[1]), "=r"((r)[2]), "=r"((r)[3])    \
                 : "r"(addr))

#define MMA2(d, a, b0, b1)                                                   \
    asm volatile("mma.sync.aligned.m16n8k16.row.col.f32.f16.f16.f32 "        \
                 "{%0,%1,%2,%3}, {%4,%5,%6,%7}, {%8,%9}, {%0,%1,%2,%3};"     \
                 : "+f"((d)[0]), "+f"((d)[1]), "+f"((d)[2]), "+f"((d)[3])    \
                 : "r"((a)[0]), "r"((a)[1]), "r"((a)[2]), "r"((a)[3]),       \
                   "r"(b0), "r"(b1))

// ---- prep 1: style (blocks 0..15) + ssq (blocks 16..527) ----------------------
__global__ void prep1_kernel(const float* __restrict__ dlat,
                             const float* __restrict__ sw,
                             const float* __restrict__ sb,
                             const int*   __restrict__ lidx,
                             const float* __restrict__ weight)
{
    int bid = blockIdx.x;
    int t = threadIdx.x;
    if (bid < NN) {
        int n = bid;
        __shared__ float dl[CC];
        int li = *lidx;
        dl[t] = dlat[(n * NWD + li) * CC + t];
        __syncthreads();
        float acc = 0.f;
#pragma unroll 4
        for (int w = 0; w < CC; ++w)
            acc += dl[w] * sw[w * CC + t];
        g_s[n * CC + t] = acc * 0.044194173824159216f + sb[t];
    } else {
        int i = bid - NN;
        float acc = 0.f;
#pragma unroll
        for (int tp = 0; tp < 9; ++tp) {
            float v = weight[(tp * CC + i) * OO + t];
            acc += v * v;
        }
        g_ssq[i * OO + t] = acc;
    }
}

// ---- prep 2: dmul[n,o] ---------------------------------------------------------
__global__ void dmul_kernel()
{
    int n = blockIdx.x;
    int o = threadIdx.x;
    __shared__ float s2[CC];
    float sv = g_s[n * CC + o];
    s2[o] = sv * sv;
    __syncthreads();
    float acc = 0.f;
#pragma unroll 4
    for (int i = 0; i < CC; ++i)
        acc += s2[i] * g_ssq[i * OO + o];
    const float ws2 = 1.0f / 4608.0f;
    const float ws  = 0.014731391274719738f;
    g_dmul[n * OO + o] = ws * rsqrtf(ws2 * acc + 1e-8f);
}

// ---- prep 3: x*s -> fp16 (blocks < 32768) + w transpose fp16 (rest) -------------
__global__ void prep3_kernel(const float* __restrict__ x,
                             const float* __restrict__ weight)
{
    int bid = blockIdx.x;
    int tid = threadIdx.x;
    if (bid < 32768) {
        int t = bid * 256 + tid;
        int e = t * 4;
        int c = e & (CC - 1);
        int n = e >> 21;
        float4 v = *(const float4*)(x + e);
        float4 s = *(const float4*)(g_s + n * CC + c);
        __half h0 = __float2half_rn(v.x * s.x);
        __half h1 = __float2half_rn(v.y * s.y);
        __half h2 = __float2half_rn(v.z * s.z);
        __half h3 = __float2half_rn(v.w * s.w);
        uint2 ph;
        ph.x = (uint32_t)__half_as_ushort(h0) | ((uint32_t)__half_as_ushort(h1) << 16);
        ph.y = (uint32_t)__half_as_ushort(h2) | ((uint32_t)__half_as_ushort(h3) << 16);
        *(uint2*)(g_xh + e) = ph;
    } else {
        __shared__ float ts[32][33];
        int wb = bid - 32768;            // 0..2303
        int tap = wb >> 8;
        int rem = wb & 255;
        int o0 = (rem & 15) * 32;
        int c0 = (rem >> 4) * 32;
        int tx = tid & 31, ty = tid >> 5;
        for (int j = ty; j < 32; j += 8)
            ts[j][tx] = weight[(tap * CC + c0 + j) * OO + o0 + tx];
        __syncthreads();
        for (int j = ty; j < 32; j += 8) {
            float v = ts[tx][j];
            int oi = (tap * OO + o0 + j) * CC + c0 + tx;
            g_wt[oi] = __float2half_rn(v);
        }
    }
}

// ---- A halo staging: 396 rows (6x66 spatial, zero-padded), kc=64 ----------------
static __device__ __forceinline__ void load_A(uint32_t dst, int c0,
                                              int n, int h0, int tid)
{
    if (tid < 396) {
        int rr = tid / 66;                 // 0..5
        int cc = tid - rr * 66;            // 0..65
        int h = h0 + rr - 1;
        int w = cc - 1;
        const bool ok = ((unsigned)h < (unsigned)HH) && ((unsigned)w < (unsigned)WW);
        const unsigned sz = ok ? 16u : 0u;
        const size_t gi = ((size_t)((n * HH + (ok ? h : 0)) * WW + (ok ? w : 0)) * CC + c0) * 2;
        const char* src = (const char*)g_xh + gi;
        const int r7 = tid & 7;
        const uint32_t rbase = dst + (uint32_t)tid * 128u;
#pragma unroll
        for (int c = 0; c < 8; ++c)
            CP16(rbase + ((c ^ r7) << 4), src + c * 16, sz);
    }
}

// ---- B staging: 128 o-rows x kc=64 (512 threads, 2x16B each) ---------------------
static __device__ __forceinline__ void load_B(uint32_t dst, int tap, int c0,
                                              int o0, int tid)
{
    const int r  = tid >> 2;               // 0..127
    const int cb = (tid & 3) * 2;          // chunk base
    const int r7 = r & 7;
    const size_t bidx = ((size_t)((tap * OO + o0 + r) * CC) + c0 + cb * 8) * 2;
    const char* src = (const char*)g_wt + bidx;
    const uint32_t rbase = dst + (uint32_t)r * 128u;
#pragma unroll
    for (int c = 0; c < 2; ++c)
        CP16(rbase + (((cb + c) ^ r7) << 4), src + c * 16, 16u);
}

// ---- kernel 4: main conv on mma.sync ----------------------------------------------
__global__ __launch_bounds__(512, 1)
void conv_mma_kernel(const float* __restrict__ bias,
                     const float* __restrict__ nstr,
                     const float* __restrict__ noise,
                     float* __restrict__ out)
{
    extern __shared__ char dynsmem[];
    const uint32_t smbase = smem_u32(dynsmem);

    const int tid  = threadIdx.x;
    const int lane = tid & 31;
    const int wid  = tid >> 5;
    const int wm   = wid & 7;          // 8 M quarters (32 rows) = 256 rows
    const int wn   = wid >> 3;         // 2 N halves (64 cols)

    const int o0 = blockIdx.x * 128;
    const int mt = blockIdx.y;         // 256 M tiles
    const int n  = mt >> 4;
    const int h0 = (mt & 15) * 4;      // 4 image rows per CTA

    // ldmatrix lane mappings
    const int a_row  = wm * 32 + (lane & 15);
    const int a_kh   = lane >> 4;
    const int bg     = lane >> 3;
    const int b_row0 = wn * 64 + ((bg >> 1) << 3) + (lane & 7);
    const int b_kh   = bg & 1;

    // A halo per-lane row bases: p = pb + (tap/3)*66 + tap%3
    const int r0 = a_row, r1 = a_row + 16;
    const int pb0 = (r0 >> 6) * 66 + (r0 & 63);
    const int pb1 = (r1 >> 6) * 66 + (r1 & 63);

    uint32_t bro[4], br7[4];
#pragma unroll
    for (int nb = 0; nb < 4; ++nb) {
        bro[nb] = (uint32_t)(b_row0 + nb * 16) * 128u;
        br7[nb] = (b_row0 + nb * 16) & 7;
    }

    float acc[2][8][4];
#pragma unroll
    for (int mi = 0; mi < 2; ++mi)
#pragma unroll
        for (int ni = 0; ni < 8; ++ni)
#pragma unroll
            for (int q = 0; q < 4; ++q) acc[mi][ni][q] = 0.f;

    // prologue: A(chunk 0) + B tiles 0,1 (slots 0,1)
    load_A(smbase, 0, n, h0, tid);
    load_B(smbase + OFF_B0 + 0 * B_BYTES, 0, 0, o0, tid);
    load_B(smbase + OFF_B0 + 1 * B_BYTES, 1, 0, o0, tid);
    CP_COMMIT();

#pragma unroll 1
    for (int k = 0; k < 8; ++k) {
        const uint32_t sbA = smbase + (k & 1) * A_BYTES;
#pragma unroll
        for (int g = 0; g < 5; ++g) {          // tap groups [2,2,2,2,1]
            CP_WAIT0();
            __syncthreads();

            // prefetch next group's B tiles (+ A for next chunk at g==1)
            {
                int gn = g + 1, kn = k;
                if (gn == 5) { gn = 0; kn = k + 1; }
                if (kn < 8) {
                    const int tapn = gn * 2;
                    const int cnt = (gn < 4) ? 2 : 1;
#pragma unroll
                    for (int q = 0; q < 2; ++q)
                        if (q < cnt) {
                            const int slot = (kn + tapn + q) & 3;  // = tile&3 (9 = 1 mod 4)
                            load_B(smbase + OFF_B0 + slot * B_BYTES,
                                   tapn + q, kn * 64, o0, tid);
                        }
                }
                if (g == 1 && k < 7)
                    load_A(smbase + ((k + 1) & 1) * A_BYTES, (k + 1) * 64, n, h0, tid);
                CP_COMMIT();
            }

            // compute group: taps g*2 (+1)
            const int cnt = (g < 4) ? 2 : 1;
#pragma unroll
            for (int q = 0; q < 2; ++q) {
                if (q < cnt) {
                    const int tap = g * 2 + q;                 // compile-time
                    const int tapoff = (tap / 3) * 66 + (tap % 3);
                    const uint32_t sbB = smbase + OFF_B0 + ((k + tap) & 3) * B_BYTES;
                    const int p0 = pb0 + tapoff;
                    const int p1 = pb1 + tapoff;
                    const uint32_t a0b = sbA + (uint32_t)p0 * 128u;
                    const uint32_t a1b = sbA + (uint32_t)p1 * 128u;
                    const int p07 = p0 & 7, p17 = p1 & 7;
#pragma unroll
                    for (int kk = 0; kk < 4; ++kk) {
                        const int rk  = (kk + wid) & 3;        // phase rotation
                        const int cha = 2 * rk + a_kh;
                        const int chb = 2 * rk + b_kh;
                        uint32_t aa[2][4], bb[4][4];
                        LDSM4(aa[0], a0b + ((cha ^ p07) << 4));
                        LDSM4(aa[1], a1b + ((cha ^ p17) << 4));
#pragma unroll
                        for (int nb = 0; nb < 4; ++nb)
                            LDSM4(bb[nb], sbB + bro[nb] + (((unsigned)chb ^ br7[nb]) << 4));
#pragma unroll
                        for (int mi = 0; mi < 2; ++mi)
#pragma unroll
                            for (int nb = 0; nb < 4; ++nb) {
                                MMA2(acc[mi][2*nb],   aa[mi], bb[nb][0], bb[nb][1]);
                                MMA2(acc[mi][2*nb+1], aa[mi], bb[nb][2], bb[nb][3]);
                            }
                    }
                }
            }
        }
    }

    // ---- epilogue: demod, noise, bias, leaky_relu * sqrt(2)
    const float nstrv = *nstr;
#pragma unroll
    for (int mi = 0; mi < 2; ++mi) {
#pragma unroll
        for (int half = 0; half < 2; ++half) {
            int m = wm * 32 + mi * 16 + (lane >> 2) + half * 8;
            int h = h0 + (m >> 6);
            int w = m & 63;
            float nz = noise[(n * HH + h) * WW + w] * nstrv;
            size_t base = ((size_t)((n * HH + h) * WW + w)) * OO + o0;
#pragma unroll
            for (int ni = 0; ni < 8; ++ni) {
                int oc = wn * 64 + ni * 8 + 2 * (lane & 3);
                float dm0 = g_dmul[n * OO + o0 + oc];
                float dm1 = g_dmul[n * OO + o0 + oc + 1];
                float b0 = bias[o0 + oc], b1 = bias[o0 + oc + 1];
                float y0 = fmaf(acc[mi][ni][half * 2],     dm0, nz + b0);
                float y1 = fmaf(acc[mi][ni][half * 2 + 1], dm1, nz + b1);
                y0 = (y0 > 0.f ? y0 : 0.2f * y0) * 1.4142135623730951f;
                y1 = (y1 > 0.f ? y1 : 0.2f * y1) * 1.4142135623730951f;
                *(float2*)(out + base + oc) = make_float2(y0, y1);
            }
        }
    }
}

// ---------------------------------------------------------------------------
extern "C" void kernel_launch(void* const* d_in, const int* in_sizes, int n_in,
                              void* d_out, int out_size)
{
    const float* x      = (const float*)d_in[0];
    const float* dlat   = (const float*)d_in[1];
    const float* sw     = (const float*)d_in[2];
    const float* sbv    = (const float*)d_in[3];
    const float* weight = (const float*)d_in[4];
    const float* bias   = (const float*)d_in[5];
    const float* nstr   = (const float*)d_in[6];
    const float* noise  = (const float*)d_in[7];
    const int*   lidx   = (const int*)  d_in[8];
    float* out = (float*)d_out;

    prep1_kernel<<<NN + CC, 512>>>(dlat, sw, sbv, lidx, weight);
    dmul_kernel<<<NN, 512>>>();
    prep3_kernel<<<32768 + 2304, 256>>>(x, weight);

    cudaFuncSetAttribute(conv_mma_kernel,
                         cudaFuncAttributeMaxDynamicSharedMemorySize, SMEM_TOTAL);
    conv_mma_kernel<<<dim3(4, 256), 512, SMEM_TOTAL>>>(bias, nstr, noise, out);
}

// round 13
// speedup vs baseline: 1.2323x; 1.2323x over previous
#include <cuda_runtime.h>
#include <cuda_fp16.h>
#include <stdint.h>

// ---------------------------------------------------------------------------
// StyleGAN2 modulated 3x3 conv, NHWC, N=16 H=W=64 C=O=512
// Round 13: R11 base (CTA 128x128, 8 warps 32x64, A-halo reuse, 2 CTAs/SM)
//           + tap-PAIR barrier intervals (5 per chunk instead of 9) using a
//           single A buffer (exposed reload at chunk boundary) and a 4-slot
//           B ring with wait_group(1) lookahead.
// ---------------------------------------------------------------------------

#define NN 16
#define HH 64
#define WW 64
#define CC 512
#define OO 512
#define NWD 14

#define A_BYTES 33792        // 264 halo rows (4x66) x 128B, kc=64
#define OFF_B0  33792
#define B_BYTES 16384        // 128 o-rows x 128B
#define SMEM_TOTAL (OFF_B0 + 4 * B_BYTES)   // 99328 -> 2 CTAs/SM

// ---- device scratch (allocation-free) --------------------------------------
__device__ float g_s[NN * CC];
__device__ float g_dmul[NN * OO];
__device__ float g_ssq[CC * OO];
__device__ __half g_xh[NN * HH * WW * CC];   // fp16(x*s)
__device__ __half g_wt[9 * OO * CC];         // fp16 w^T [tap][o][c]

// ---- helpers -----------------------------------------------------------------
static __device__ __forceinline__ uint32_t smem_u32(const void* p) {
    uint32_t a;
    asm("{ .reg .u64 t; cvta.to.shared.u64 t, %1; cvt.u32.u64 %0, t; }"
        : "=r"(a) : "l"(p));
    return a;
}

#define CP16(dst, src, sz)                                                   \
    asm volatile("cp.async.cg.shared.global [%0], [%1], 16, %2;"             \
                 :: "r"(dst), "l"(src), "r"(sz) : "memory")
#define CP_COMMIT() asm volatile("cp.async.commit_group;" ::: "memory")
#define CP_WAIT1()  asm volatile("cp.async.wait_group 1;" ::: "memory")
#define CP_WAIT0()  asm volatile("cp.async.wait_group 0;" ::: "memory")

#define LDSM4(r, addr)                                                       \
    asm volatile("ldmatrix.sync.aligned.m8n8.x4.shared.b16 "                 \
                 "{%0,%1,%2,%3}, [%4];"                                      \
                 : "=r"((r)[0]), "=r"((r)[1]), "=r"((r)[2]), "=r"((r)[3])    \
                 : "r"(addr))

#define MMA2(d, a, b0, b1)                                                   \
    asm volatile("mma.sync.aligned.m16n8k16.row.col.f32.f16.f16.f32 "        \
                 "{%0,%1,%2,%3}, {%4,%5,%6,%7}, {%8,%9}, {%0,%1,%2,%3};"     \
                 : "+f"((d)[0]), "+f"((d)[1]), "+f"((d)[2]), "+f"((d)[3])    \
                 : "r"((a)[0]), "r"((a)[1]), "r"((a)[2]), "r"((a)[3]),       \
                   "r"(b0), "r"(b1))

// ---- prep 1: style (blocks 0..15) + ssq (blocks 16..527) ----------------------
__global__ void prep1_kernel(const float* __restrict__ dlat,
                             const float* __restrict__ sw,
                             const float* __restrict__ sb,
                             const int*   __restrict__ lidx,
                             const float* __restrict__ weight)
{
    int bid = blockIdx.x;
    int t = threadIdx.x;
    if (bid < NN) {
        int n = bid;
        __shared__ float dl[CC];
        int li = *lidx;
        dl[t] = dlat[(n * NWD + li) * CC + t];
        __syncthreads();
        float acc = 0.f;
#pragma unroll 4
        for (int w = 0; w < CC; ++w)
            acc += dl[w] * sw[w * CC + t];
        g_s[n * CC + t] = acc * 0.044194173824159216f + sb[t];
    } else {
        int i = bid - NN;
        float acc = 0.f;
#pragma unroll
        for (int tp = 0; tp < 9; ++tp) {
            float v = weight[(tp * CC + i) * OO + t];
            acc += v * v;
        }
        g_ssq[i * OO + t] = acc;
    }
}

// ---- prep 2: dmul[n,o] ---------------------------------------------------------
__global__ void dmul_kernel()
{
    int n = blockIdx.x;
    int o = threadIdx.x;
    __shared__ float s2[CC];
    float sv = g_s[n * CC + o];
    s2[o] = sv * sv;
    __syncthreads();
    float acc = 0.f;
#pragma unroll 4
    for (int i = 0; i < CC; ++i)
        acc += s2[i] * g_ssq[i * OO + o];
    const float ws2 = 1.0f / 4608.0f;
    const float ws  = 0.014731391274719738f;
    g_dmul[n * OO + o] = ws * rsqrtf(ws2 * acc + 1e-8f);
}

// ---- prep 3: x*s -> fp16 (blocks < 32768) + w transpose fp16 (rest) -------------
__global__ void prep3_kernel(const float* __restrict__ x,
                             const float* __restrict__ weight)
{
    int bid = blockIdx.x;
    int tid = threadIdx.x;
    if (bid < 32768) {
        int t = bid * 256 + tid;
        int e = t * 4;
        int c = e & (CC - 1);
        int n = e >> 21;
        float4 v = *(const float4*)(x + e);
        float4 s = *(const float4*)(g_s + n * CC + c);
        __half h0 = __float2half_rn(v.x * s.x);
        __half h1 = __float2half_rn(v.y * s.y);
        __half h2 = __float2half_rn(v.z * s.z);
        __half h3 = __float2half_rn(v.w * s.w);
        uint2 ph;
        ph.x = (uint32_t)__half_as_ushort(h0) | ((uint32_t)__half_as_ushort(h1) << 16);
        ph.y = (uint32_t)__half_as_ushort(h2) | ((uint32_t)__half_as_ushort(h3) << 16);
        *(uint2*)(g_xh + e) = ph;
    } else {
        __shared__ float ts[32][33];
        int wb = bid - 32768;            // 0..2303
        int tap = wb >> 8;
        int rem = wb & 255;
        int o0 = (rem & 15) * 32;
        int c0 = (rem >> 4) * 32;
        int tx = tid & 31, ty = tid >> 5;
        for (int j = ty; j < 32; j += 8)
            ts[j][tx] = weight[(tap * CC + c0 + j) * OO + o0 + tx];
        __syncthreads();
        for (int j = ty; j < 32; j += 8) {
            float v = ts[tx][j];
            int oi = (tap * OO + o0 + j) * CC + c0 + tx;
            g_wt[oi] = __float2half_rn(v);
        }
    }
}

// ---- A halo staging: 264 rows (4x66 spatial, zero-padded), kc=64 ----------------
static __device__ __forceinline__ void load_A(uint32_t dst, int c0,
                                              int n, int h0, int tid)
{
#pragma unroll
    for (int it = 0; it < 2; ++it) {
        int row = tid + it * 256;
        if (row < 264) {
            int rr = row >= 198 ? 3 : (row >= 132 ? 2 : (row >= 66 ? 1 : 0));
            int cc = row - rr * 66;
            int h = h0 + rr - 1;
            int w = cc - 1;
            const bool ok = ((unsigned)h < (unsigned)HH) && ((unsigned)w < (unsigned)WW);
            const unsigned sz = ok ? 16u : 0u;
            const size_t gi = ((size_t)((n * HH + (ok ? h : 0)) * WW + (ok ? w : 0)) * CC + c0) * 2;
            const char* src = (const char*)g_xh + gi;
            const int r7 = row & 7;
            const uint32_t rbase = dst + (uint32_t)row * 128u;
#pragma unroll
            for (int c = 0; c < 8; ++c)
                CP16(rbase + ((c ^ r7) << 4), src + c * 16, sz);
        }
    }
}

// ---- B staging: 128 o-rows x kc=64 (256 threads, 4x16B each) ---------------------
static __device__ __forceinline__ void load_B(uint32_t dst, int tap, int c0,
                                              int o0, int tid)
{
    const int r  = tid >> 1;
    const int cb = (tid & 1) * 4;
    const int r7 = r & 7;
    const size_t bidx = ((size_t)((tap * OO + o0 + r) * CC) + c0 + cb * 8) * 2;
    const char* src = (const char*)g_wt + bidx;
    const uint32_t rbase = dst + (uint32_t)r * 128u;
#pragma unroll
    for (int c = 0; c < 4; ++c)
        CP16(rbase + (((cb + c) ^ r7) << 4), src + c * 16, 16u);
}

// ---- kernel 4: main conv on mma.sync ----------------------------------------------
__global__ __launch_bounds__(256, 2)
void conv_mma_kernel(const float* __restrict__ bias,
                     const float* __restrict__ nstr,
                     const float* __restrict__ noise,
                     float* __restrict__ out)
{
    extern __shared__ char dynsmem[];
    const uint32_t smbase = smem_u32(dynsmem);

    const int tid  = threadIdx.x;
    const int lane = tid & 31;
    const int wid  = tid >> 5;
    const int wm   = wid & 3;          // M quarter (32 rows)
    const int wn   = wid >> 2;         // N half (64 cols)

    const int o0 = blockIdx.x * 128;
    const int mt = blockIdx.y;
    const int n  = mt >> 5;
    const int h0 = (mt & 31) * 2;

    // ldmatrix lane mappings
    const int a_row  = wm * 32 + (lane & 15);
    const int a_kh   = lane >> 4;
    const int bg     = lane >> 3;
    const int b_row0 = wn * 64 + ((bg >> 1) << 3) + (lane & 7);
    const int b_kh   = bg & 1;

    const int r0 = a_row, r1 = a_row + 16;
    const int pb0 = (r0 >> 6) * 66 + (r0 & 63);
    const int pb1 = (r1 >> 6) * 66 + (r1 & 63);

    uint32_t bro[4], br7[4];
#pragma unroll
    for (int nb = 0; nb < 4; ++nb) {
        bro[nb] = (uint32_t)(b_row0 + nb * 16) * 128u;
        br7[nb] = (b_row0 + nb * 16) & 7;
    }

    float acc[2][8][4];
#pragma unroll
    for (int mi = 0; mi < 2; ++mi)
#pragma unroll
        for (int ni = 0; ni < 8; ++ni)
#pragma unroll
            for (int q = 0; q < 4; ++q) acc[mi][ni][q] = 0.f;

// one tap's worth of MMAs (tap is a compile-time constant at each expansion)
#define COMPUTE_TAP(TAP) do {                                                 \
    const int _toff = ((TAP) / 3) * 66 + ((TAP) % 3);                         \
    const uint32_t sbB = smbase + OFF_B0 + (((k + (TAP)) & 3) * B_BYTES);     \
    const int _p0 = pb0 + _toff, _p1 = pb1 + _toff;                           \
    const uint32_t a0b = smbase + (uint32_t)_p0 * 128u;                       \
    const uint32_t a1b = smbase + (uint32_t)_p1 * 128u;                       \
    const int p07 = _p0 & 7, p17 = _p1 & 7;                                   \
    _Pragma("unroll")                                                         \
    for (int kk = 0; kk < 4; ++kk) {                                          \
        const int rk  = (kk + wid) & 3;                                       \
        const int cha = 2 * rk + a_kh;                                        \
        const int chb = 2 * rk + b_kh;                                        \
        uint32_t aa[2][4], bb[4][4];                                          \
        LDSM4(aa[0], a0b + ((cha ^ p07) << 4));                               \
        LDSM4(aa[1], a1b + ((cha ^ p17) << 4));                               \
        _Pragma("unroll")                                                     \
        for (int nb = 0; nb < 4; ++nb)                                        \
            LDSM4(bb[nb], sbB + bro[nb] + (((unsigned)chb ^ br7[nb]) << 4));  \
        _Pragma("unroll")                                                     \
        for (int mi = 0; mi < 2; ++mi)                                        \
            _Pragma("unroll")                                                 \
            for (int nb = 0; nb < 4; ++nb) {                                  \
                MMA2(acc[mi][2*nb],   aa[mi], bb[nb][0], bb[nb][1]);          \
                MMA2(acc[mi][2*nb+1], aa[mi], bb[nb][2], bb[nb][3]);          \
            }                                                                 \
    }                                                                         \
} while (0)

    const uint32_t sB = smbase + OFF_B0;

    // prologue: A(chunk0); B taps 0,1 (commit 1); B taps 2,3 (commit 2)
    load_A(smbase, 0, n, h0, tid);
    load_B(sB + ((0 + 0) & 3) * B_BYTES, 0, 0, o0, tid);
    load_B(sB + ((0 + 1) & 3) * B_BYTES, 1, 0, o0, tid);
    CP_COMMIT();
    load_B(sB + ((0 + 2) & 3) * B_BYTES, 2, 0, o0, tid);
    load_B(sB + ((0 + 3) & 3) * B_BYTES, 3, 0, o0, tid);
    CP_COMMIT();
    CP_WAIT1();            // A + taps 0,1 resident
    __syncthreads();

#pragma unroll 1
    for (int k = 0; k < 8; ++k) {
        const int c0n = (k + 1) * 64;
        // ---- g=0: taps 0,1
        COMPUTE_TAP(0); COMPUTE_TAP(1);
        __syncthreads();
        load_B(sB + ((k + 4) & 3) * B_BYTES, 4, k * 64, o0, tid);
        load_B(sB + ((k + 5) & 3) * B_BYTES, 5, k * 64, o0, tid);
        CP_COMMIT(); CP_WAIT1(); __syncthreads();
        // ---- g=1: taps 2,3
        COMPUTE_TAP(2); COMPUTE_TAP(3);
        __syncthreads();
        load_B(sB + ((k + 6) & 3) * B_BYTES, 6, k * 64, o0, tid);
        load_B(sB + ((k + 7) & 3) * B_BYTES, 7, k * 64, o0, tid);
        CP_COMMIT(); CP_WAIT1(); __syncthreads();
        // ---- g=2: taps 4,5
        COMPUTE_TAP(4); COMPUTE_TAP(5);
        __syncthreads();
        load_B(sB + ((k + 8) & 3) * B_BYTES, 8, k * 64, o0, tid);
        CP_COMMIT(); CP_WAIT1(); __syncthreads();
        // ---- g=3: taps 6,7
        COMPUTE_TAP(6); COMPUTE_TAP(7);
        __syncthreads();
        if (k < 7) {       // prefetch next chunk's taps 0,1 (slots k+1, k+2 mod 4)
            load_B(sB + ((k + 1 + 0) & 3) * B_BYTES, 0, c0n, o0, tid);
            load_B(sB + ((k + 1 + 1) & 3) * B_BYTES, 1, c0n, o0, tid);
        }
        CP_COMMIT(); CP_WAIT1(); __syncthreads();
        // ---- g=4: tap 8
        COMPUTE_TAP(8);
        __syncthreads();
        if (k < 7) {       // exposed A reload + next chunk's taps 2,3
            load_A(smbase, c0n, n, h0, tid);
            load_B(sB + ((k + 1 + 2) & 3) * B_BYTES, 2, c0n, o0, tid);
            load_B(sB + ((k + 1 + 3) & 3) * B_BYTES, 3, c0n, o0, tid);
        }
        CP_COMMIT(); CP_WAIT0(); __syncthreads();
    }
#undef COMPUTE_TAP

    // ---- epilogue: demod, noise, bias, leaky_relu * sqrt(2)
    const float nstrv = *nstr;
#pragma unroll
    for (int mi = 0; mi < 2; ++mi) {
#pragma unroll
        for (int half = 0; half < 2; ++half) {
            int m = wm * 32 + mi * 16 + (lane >> 2) + half * 8;
            int h = h0 + (m >> 6);
            int w = m & 63;
            float nz = noise[(n * HH + h) * WW + w] * nstrv;
            size_t base = ((size_t)((n * HH + h) * WW + w)) * OO + o0;
#pragma unroll
            for (int ni = 0; ni < 8; ++ni) {
                int oc = wn * 64 + ni * 8 + 2 * (lane & 3);
                float dm0 = g_dmul[n * OO + o0 + oc];
                float dm1 = g_dmul[n * OO + o0 + oc + 1];
                float b0 = bias[o0 + oc], b1 = bias[o0 + oc + 1];
                float y0 = fmaf(acc[mi][ni][half * 2],     dm0, nz + b0);
                float y1 = fmaf(acc[mi][ni][half * 2 + 1], dm1, nz + b1);
                y0 = (y0 > 0.f ? y0 : 0.2f * y0) * 1.4142135623730951f;
                y1 = (y1 > 0.f ? y1 : 0.2f * y1) * 1.4142135623730951f;
                *(float2*)(out + base + oc) = make_float2(y0, y1);
            }
        }
    }
}

// ---------------------------------------------------------------------------
extern "C" void kernel_launch(void* const* d_in, const int* in_sizes, int n_in,
                              void* d_out, int out_size)
{
    const float* x      = (const float*)d_in[0];
    const float* dlat   = (const float*)d_in[1];
    const float* sw     = (const float*)d_in[2];
    const float* sbv    = (const float*)d_in[3];
    const float* weight = (const float*)d_in[4];
    const float* bias   = (const float*)d_in[5];
    const float* nstr   = (const float*)d_in[6];
    const float* noise  = (const float*)d_in[7];
    const int*   lidx   = (const int*)  d_in[8];
    float* out = (float*)d_out;

    prep1_kernel<<<NN + CC, 512>>>(dlat, sw, sbv, lidx, weight);
    dmul_kernel<<<NN, 512>>>();
    prep3_kernel<<<32768 + 2304, 256>>>(x, weight);

    cudaFuncSetAttribute(conv_mma_kernel,
                         cudaFuncAttributeMaxDynamicSharedMemorySize, SMEM_TOTAL);
    conv_mma_kernel<<<dim3(4, 512), 256, SMEM_TOTAL>>>(bias, nstr, noise, out);
}

// round 14
// speedup vs baseline: 1.3540x; 1.0988x over previous
#include <cuda_runtime.h>
#include <cuda_fp16.h>
#include <stdint.h>

// ---------------------------------------------------------------------------
// StyleGAN2 modulated 3x3 conv, NHWC, N=16 H=W=64 C=O=512
// Round 14: conv = R11 verbatim (best known: 857us, tensor 59%).
//           Prep chain collapsed 3->2 launches with tiny 16-CTA jobs
//           (style GEMV, dmul) overlapped with wide work (ssq/wsplit, xsplit).
// ---------------------------------------------------------------------------

#define NN 16
#define HH 64
#define WW 64
#define CC 512
#define OO 512
#define NWD 14

#define A_BYTES 33792        // 264 halo rows x 128B  (4x66 spatial, kc=64)
#define OFF_B0  67584        // after 2 A buffers
#define B_BYTES 16384        // 128 o-rows x 128B
#define SMEM_TOTAL (OFF_B0 + 2 * B_BYTES)   // 100352
#define NCHUNK 72            // 9 taps x 8 c-chunks

// ---- device scratch (allocation-free) --------------------------------------
__device__ float g_s[NN * CC];
__device__ float g_dmul[NN * OO];
__device__ float g_ssq[CC * OO];
__device__ __half g_xh[NN * HH * WW * CC];   // fp16(x*s)
__device__ __half g_wt[9 * OO * CC];         // fp16 w^T [tap][o][c]

// ---- helpers -----------------------------------------------------------------
static __device__ __forceinline__ uint32_t smem_u32(const void* p) {
    uint32_t a;
    asm("{ .reg .u64 t; cvta.to.shared.u64 t, %1; cvt.u32.u64 %0, t; }"
        : "=r"(a) : "l"(p));
    return a;
}

#define CP16(dst, src, sz)                                                   \
    asm volatile("cp.async.cg.shared.global [%0], [%1], 16, %2;"             \
                 :: "r"(dst), "l"(src), "r"(sz) : "memory")
#define CP_COMMIT() asm volatile("cp.async.commit_group;" ::: "memory")
#define CP_WAIT0()  asm volatile("cp.async.wait_group 0;" ::: "memory")

#define LDSM4(r, addr)                                                       \
    asm volatile("ldmatrix.sync.aligned.m8n8.x4.shared.b16 "                 \
                 "{%0,%1,%2,%3}, [%4];"                                      \
                 : "=r"((r)[0]), "=r"((r)[1]), "=r"((r)[2]), "=r"((r)[3])    \
                 : "r"(addr))

#define MMA2(d, a, b0, b1)                                                   \
    asm volatile("mma.sync.aligned.m16n8k16.row.col.f32.f16.f16.f32 "        \
                 "{%0,%1,%2,%3}, {%4,%5,%6,%7}, {%8,%9}, {%0,%1,%2,%3};"     \
                 : "+f"((d)[0]), "+f"((d)[1]), "+f"((d)[2]), "+f"((d)[3])    \
                 : "r"((a)[0]), "r"((a)[1]), "r"((a)[2]), "r"((a)[3]),       \
                   "r"(b0), "r"(b1))

// ---- prep_a: style (0..15) | ssq (16..527) | w transpose fp16 (528..1679) -------
__global__ void prep_a_kernel(const float* __restrict__ dlat,
                              const float* __restrict__ sw,
                              const float* __restrict__ sb,
                              const int*   __restrict__ lidx,
                              const float* __restrict__ weight)
{
    int bid = blockIdx.x;
    int tid = threadIdx.x;
    if (bid < NN) {
        int n = bid;
        __shared__ float dl[CC];
        int li = *lidx;
        dl[tid] = dlat[(n * NWD + li) * CC + tid];
        __syncthreads();
        float acc = 0.f;
#pragma unroll 4
        for (int w = 0; w < CC; ++w)
            acc += dl[w] * sw[w * CC + tid];
        g_s[n * CC + tid] = acc * 0.044194173824159216f + sb[tid];
    } else if (bid < NN + CC) {
        int i = bid - NN;
        float acc = 0.f;
#pragma unroll
        for (int tp = 0; tp < 9; ++tp) {
            float v = weight[(tp * CC + i) * OO + tid];
            acc += v * v;
        }
        g_ssq[i * OO + tid] = acc;
    } else {
        // w transpose + fp16: two 32x32 tiles per block (512 threads)
        __shared__ float ts[2][32][33];
        int sub = tid >> 8;              // 0/1
        int st  = tid & 255;
        int wb  = (bid - (NN + CC)) * 2 + sub;   // 0..2303
        int tap = wb >> 8;
        int rem = wb & 255;
        int o0 = (rem & 15) * 32;
        int c0 = (rem >> 4) * 32;
        int tx = st & 31, ty = st >> 5;
        for (int j = ty; j < 32; j += 8)
            ts[sub][j][tx] = weight[(tap * CC + c0 + j) * OO + o0 + tx];
        __syncthreads();
        for (int j = ty; j < 32; j += 8) {
            float v = ts[sub][tx][j];
            int oi = (tap * OO + o0 + j) * CC + c0 + tx;
            g_wt[oi] = __float2half_rn(v);
        }
    }
}

// ---- prep_b: dmul (blocks 0..15) | xsplit fp16 (rest) ---------------------------
__global__ void prep_b_kernel(const float* __restrict__ x)
{
    int bid = blockIdx.x;
    int tid = threadIdx.x;
    if (bid < NN) {
        int n = bid;
        int o = tid;
        __shared__ float s2[CC];
        float sv = g_s[n * CC + o];
        s2[o] = sv * sv;
        __syncthreads();
        float acc = 0.f;
#pragma unroll 4
        for (int i = 0; i < CC; ++i)
            acc += s2[i] * g_ssq[i * OO + o];
        const float ws2 = 1.0f / 4608.0f;
        const float ws  = 0.014731391274719738f;
        g_dmul[n * OO + o] = ws * rsqrtf(ws2 * acc + 1e-8f);
    } else {
        int t = (bid - NN) * 512 + tid;
        int e = t * 4;
        int c = e & (CC - 1);
        int n = e >> 21;
        float4 v = *(const float4*)(x + e);
        float4 s = *(const float4*)(g_s + n * CC + c);
        __half h0 = __float2half_rn(v.x * s.x);
        __half h1 = __float2half_rn(v.y * s.y);
        __half h2 = __float2half_rn(v.z * s.z);
        __half h3 = __float2half_rn(v.w * s.w);
        uint2 ph;
        ph.x = (uint32_t)__half_as_ushort(h0) | ((uint32_t)__half_as_ushort(h1) << 16);
        ph.y = (uint32_t)__half_as_ushort(h2) | ((uint32_t)__half_as_ushort(h3) << 16);
        *(uint2*)(g_xh + e) = ph;
    }
}

// ---- A halo staging: 264 rows (4x66 spatial, zero-padded), kc=64 ----------------
static __device__ __forceinline__ void load_A(uint32_t dst, int c0,
                                              int n, int h0, int tid)
{
#pragma unroll
    for (int it = 0; it < 2; ++it) {
        int row = tid + it * 256;
        if (row < 264) {
            int rr = row >= 198 ? 3 : (row >= 132 ? 2 : (row >= 66 ? 1 : 0));
            int cc = row - rr * 66;
            int h = h0 + rr - 1;
            int w = cc - 1;
            const bool ok = ((unsigned)h < (unsigned)HH) && ((unsigned)w < (unsigned)WW);
            const unsigned sz = ok ? 16u : 0u;
            const size_t gi = ((size_t)((n * HH + (ok ? h : 0)) * WW + (ok ? w : 0)) * CC + c0) * 2;
            const char* src = (const char*)g_xh + gi;
            const int r7 = row & 7;
            const uint32_t rbase = dst + (uint32_t)row * 128u;
#pragma unroll
            for (int c = 0; c < 8; ++c)
                CP16(rbase + ((c ^ r7) << 4), src + c * 16, sz);
        }
    }
}

// ---- B staging: 128 o-rows x kc=64 ------------------------------------------------
static __device__ __forceinline__ void load_B(uint32_t dst, int tap, int c0,
                                               int o0, int tid)
{
    const int r  = tid >> 1;
    const int cb = (tid & 1) * 4;
    const int r7 = r & 7;
    const size_t bidx = ((size_t)((tap * OO + o0 + r) * CC) + c0 + cb * 8) * 2;
    const char* src = (const char*)g_wt + bidx;
    const uint32_t rbase = dst + (uint32_t)r * 128u;
#pragma unroll
    for (int c = 0; c < 4; ++c)
        CP16(rbase + (((cb + c) ^ r7) << 4), src + c * 16, 16u);
}

// ---- main conv on mma.sync (R11 verbatim) ------------------------------------------
__global__ __launch_bounds__(256, 2)
void conv_mma_kernel(const float* __restrict__ bias,
                     const float* __restrict__ nstr,
                     const float* __restrict__ noise,
                     float* __restrict__ out)
{
    extern __shared__ char dynsmem[];
    const uint32_t smbase = smem_u32(dynsmem);

    const int tid  = threadIdx.x;
    const int lane = tid & 31;
    const int wid  = tid >> 5;
    const int wm   = wid & 3;          // M quarter (32 rows)
    const int wn   = wid >> 2;         // N half (64 cols)

    const int o0 = blockIdx.x * 128;
    const int mt = blockIdx.y;
    const int n  = mt >> 5;
    const int h0 = (mt & 31) * 2;

    // ldmatrix lane mappings
    const int a_row  = wm * 32 + (lane & 15);
    const int a_kh   = lane >> 4;
    const int bg     = lane >> 3;
    const int b_row0 = wn * 64 + ((bg >> 1) << 3) + (lane & 7);
    const int b_kh   = bg & 1;

    // A halo per-lane row bases (pb for mi=0,1): p = pb + tapoff
    const int r0 = a_row,      r1 = a_row + 16;
    const int pb0 = (r0 >> 6) * 66 + (r0 & 63);
    const int pb1 = (r1 >> 6) * 66 + (r1 & 63);

    // B fragment row offsets within B buffer
    uint32_t bro[4], br7[4];
#pragma unroll
    for (int nb = 0; nb < 4; ++nb) {
        bro[nb] = (uint32_t)(b_row0 + nb * 16) * 128u;
        br7[nb] = (b_row0 + nb * 16) & 7;
    }

    float acc[2][8][4];
#pragma unroll
    for (int mi = 0; mi < 2; ++mi)
#pragma unroll
        for (int ni = 0; ni < 8; ++ni)
#pragma unroll
            for (int q = 0; q < 4; ++q) acc[mi][ni][q] = 0.f;

    // prologue: A(chunk 0) + B(tap 0, chunk 0)
    load_A(smbase, 0, n, h0, tid);
    load_B(smbase + OFF_B0, 0, 0, o0, tid);
    CP_COMMIT();

    int tap = 0, k = 0, tapoff = 0;
#pragma unroll 1
    for (int i = 0; i < NCHUNK; ++i) {
        CP_WAIT0();          // own copies for chunk i done
        __syncthreads();     // all visible; all finished reading bufs of i-1

        // issue loads for i+1 (B) and, mid-chunk, A for next c-chunk
        if (i + 1 < NCHUNK) {
            int tapj = tap + 1, kj = k;
            if (tapj == 9) { tapj = 0; ++kj; }
            load_B(smbase + OFF_B0 + ((i + 1) & 1) * B_BYTES, tapj, kj * 64, o0, tid);
            if (tap == 3 && k + 1 < 8)
                load_A(smbase + ((k + 1) & 1) * A_BYTES, (k + 1) * 64, n, h0, tid);
        }
        CP_COMMIT();

        const uint32_t sbA = smbase + (k & 1) * A_BYTES;
        const uint32_t sbB = smbase + OFF_B0 + (i & 1) * B_BYTES;
        const int p0 = pb0 + tapoff;
        const int p1 = pb1 + tapoff;
        const uint32_t a0b = sbA + (uint32_t)p0 * 128u;
        const uint32_t a1b = sbA + (uint32_t)p1 * 128u;
        const int p07 = p0 & 7, p17 = p1 & 7;

#pragma unroll
        for (int kk = 0; kk < 4; ++kk) {
            const int rk  = (kk + wid) & 3;          // per-warp phase rotation
            const int cha = 2 * rk + a_kh;
            const int chb = 2 * rk + b_kh;
            uint32_t aa[2][4], bb[4][4];
            LDSM4(aa[0], a0b + ((cha ^ p07) << 4));
            LDSM4(aa[1], a1b + ((cha ^ p17) << 4));
#pragma unroll
            for (int nb = 0; nb < 4; ++nb)
                LDSM4(bb[nb], sbB + bro[nb] + (((unsigned)chb ^ br7[nb]) << 4));
#pragma unroll
            for (int mi = 0; mi < 2; ++mi)
#pragma unroll
                for (int nb = 0; nb < 4; ++nb) {
                    MMA2(acc[mi][2*nb],   aa[mi], bb[nb][0], bb[nb][1]);
                    MMA2(acc[mi][2*nb+1], aa[mi], bb[nb][2], bb[nb][3]);
                }
        }

        if (++tap == 9) { tap = 0; ++k; tapoff = 0; }
        else tapoff += ((tap == 3 || tap == 6) ? 64 : 1);
    }

    // ---- epilogue: demod, noise, bias, leaky_relu * sqrt(2)
    const float nstrv = *nstr;
#pragma unroll
    for (int mi = 0; mi < 2; ++mi) {
#pragma unroll
        for (int half = 0; half < 2; ++half) {
            int m = wm * 32 + mi * 16 + (lane >> 2) + half * 8;
            int h = h0 + (m >> 6);
            int w = m & 63;
            float nz = noise[(n * HH + h) * WW + w] * nstrv;
            size_t base = ((size_t)((n * HH + h) * WW + w)) * OO + o0;
#pragma unroll
            for (int ni = 0; ni < 8; ++ni) {
                int oc = wn * 64 + ni * 8 + 2 * (lane & 3);
                float dm0 = g_dmul[n * OO + o0 + oc];
                float dm1 = g_dmul[n * OO + o0 + oc + 1];
                float b0 = bias[o0 + oc], b1 = bias[o0 + oc + 1];
                float y0 = fmaf(acc[mi][ni][half * 2],     dm0, nz + b0);
                float y1 = fmaf(acc[mi][ni][half * 2 + 1], dm1, nz + b1);
                y0 = (y0 > 0.f ? y0 : 0.2f * y0) * 1.4142135623730951f;
                y1 = (y1 > 0.f ? y1 : 0.2f * y1) * 1.4142135623730951f;
                *(float2*)(out + base + oc) = make_float2(y0, y1);
            }
        }
    }
}

// ---------------------------------------------------------------------------
extern "C" void kernel_launch(void* const* d_in, const int* in_sizes, int n_in,
                              void* d_out, int out_size)
{
    const float* x      = (const float*)d_in[0];
    const float* dlat   = (const float*)d_in[1];
    const float* sw     = (const float*)d_in[2];
    const float* sbv    = (const float*)d_in[3];
    const float* weight = (const float*)d_in[4];
    const float* bias   = (const float*)d_in[5];
    const float* nstr   = (const float*)d_in[6];
    const float* noise  = (const float*)d_in[7];
    const int*   lidx   = (const int*)  d_in[8];
    float* out = (float*)d_out;

    // prep_a: style | ssq | w transpose  (all independent)
    prep_a_kernel<<<NN + CC + 1152, 512>>>(dlat, sw, sbv, lidx, weight);
    // prep_b: dmul | xsplit  (both depend only on prep_a)
    prep_b_kernel<<<NN + 16384, 512>>>(x);

    cudaFuncSetAttribute(conv_mma_kernel,
                         cudaFuncAttributeMaxDynamicSharedMemorySize, SMEM_TOTAL);
    conv_mma_kernel<<<dim3(4, 512), 256, SMEM_TOTAL>>>(bias, nstr, noise, out);
}

// round 15
// speedup vs baseline: 1.3588x; 1.0035x over previous
#include <cuda_runtime.h>
#include <cuda_fp16.h>
#include <stdint.h>

// ---------------------------------------------------------------------------
// StyleGAN2 modulated 3x3 conv, NHWC, N=16 H=W=64 C=O=512
// Round 15: conv = R11 skeleton with tap-PAIR intervals (6 syncs/chunk vs 9):
//           single A halo buffer (exposed reload at chunk boundary),
//           B double buffer of 32KB holding a tap pair. 2 CTAs/SM.
//           Prep: 4-accumulator ILP in style/dmul serial loops.
// ---------------------------------------------------------------------------

#define NN 16
#define HH 64
#define WW 64
#define CC 512
#define OO 512
#define NWD 14

#define A_BYTES 33792        // 264 halo rows x 128B (4x66 spatial, kc=64)
#define OFF_B0  33792        // B double buffer starts after single A buffer
#define BPAIR   32768        // one B buffer = 2 taps x 16KB
#define SMEM_TOTAL (OFF_B0 + 2 * BPAIR)   // 99328 -> 2 CTAs/SM

// ---- device scratch (allocation-free) --------------------------------------
__device__ float g_s[NN * CC];
__device__ float g_dmul[NN * OO];
__device__ float g_ssq[CC * OO];
__device__ __half g_xh[NN * HH * WW * CC];   // fp16(x*s)
__device__ __half g_wt[9 * OO * CC];         // fp16 w^T [tap][o][c]

// ---- helpers -----------------------------------------------------------------
static __device__ __forceinline__ uint32_t smem_u32(const void* p) {
    uint32_t a;
    asm("{ .reg .u64 t; cvta.to.shared.u64 t, %1; cvt.u32.u64 %0, t; }"
        : "=r"(a) : "l"(p));
    return a;
}

#define CP16(dst, src, sz)                                                   \
    asm volatile("cp.async.cg.shared.global [%0], [%1], 16, %2;"             \
                 :: "r"(dst), "l"(src), "r"(sz) : "memory")
#define CP_COMMIT() asm volatile("cp.async.commit_group;" ::: "memory")
#define CP_WAIT0()  asm volatile("cp.async.wait_group 0;" ::: "memory")

#define LDSM4(r, addr)                                                       \
    asm volatile("ldmatrix.sync.aligned.m8n8.x4.shared.b16 "                 \
                 "{%0,%1,%2,%3}, [%4];"                                      \
                 : "=r"((r)[0]), "=r"((r)[1]), "=r"((r)[2]), "=r"((r)[3])    \
                 : "r"(addr))

#define MMA2(d, a, b0, b1)                                                   \
    asm volatile("mma.sync.aligned.m16n8k16.row.col.f32.f16.f16.f32 "        \
                 "{%0,%1,%2,%3}, {%4,%5,%6,%7}, {%8,%9}, {%0,%1,%2,%3};"     \
                 : "+f"((d)[0]), "+f"((d)[1]), "+f"((d)[2]), "+f"((d)[3])    \
                 : "r"((a)[0]), "r"((a)[1]), "r"((a)[2]), "r"((a)[3]),       \
                   "r"(b0), "r"(b1))

// ---- prep_a: style (0..15) | ssq (16..527) | w transpose fp16 (528..1679) -------
__global__ void prep_a_kernel(const float* __restrict__ dlat,
                              const float* __restrict__ sw,
                              const float* __restrict__ sb,
                              const int*   __restrict__ lidx,
                              const float* __restrict__ weight)
{
    int bid = blockIdx.x;
    int tid = threadIdx.x;
    if (bid < NN) {
        int n = bid;
        __shared__ float dl[CC];
        int li = *lidx;
        dl[tid] = dlat[(n * NWD + li) * CC + tid];
        __syncthreads();
        float a0 = 0.f, a1 = 0.f, a2 = 0.f, a3 = 0.f;
#pragma unroll 2
        for (int w = 0; w < CC; w += 4) {
            a0 += dl[w]     * sw[(w)     * CC + tid];
            a1 += dl[w + 1] * sw[(w + 1) * CC + tid];
            a2 += dl[w + 2] * sw[(w + 2) * CC + tid];
            a3 += dl[w + 3] * sw[(w + 3) * CC + tid];
        }
        g_s[n * CC + tid] = ((a0 + a1) + (a2 + a3)) * 0.044194173824159216f + sb[tid];
    } else if (bid < NN + CC) {
        int i = bid - NN;
        float acc = 0.f;
#pragma unroll
        for (int tp = 0; tp < 9; ++tp) {
            float v = weight[(tp * CC + i) * OO + tid];
            acc += v * v;
        }
        g_ssq[i * OO + tid] = acc;
    } else {
        __shared__ float ts[2][32][33];
        int sub = tid >> 8;
        int st  = tid & 255;
        int wb  = (bid - (NN + CC)) * 2 + sub;   // 0..2303
        int tap = wb >> 8;
        int rem = wb & 255;
        int o0 = (rem & 15) * 32;
        int c0 = (rem >> 4) * 32;
        int tx = st & 31, ty = st >> 5;
        for (int j = ty; j < 32; j += 8)
            ts[sub][j][tx] = weight[(tap * CC + c0 + j) * OO + o0 + tx];
        __syncthreads();
        for (int j = ty; j < 32; j += 8) {
            float v = ts[sub][tx][j];
            int oi = (tap * OO + o0 + j) * CC + c0 + tx;
            g_wt[oi] = __float2half_rn(v);
        }
    }
}

// ---- prep_b: dmul (blocks 0..15) | xsplit fp16 (rest) ---------------------------
__global__ void prep_b_kernel(const float* __restrict__ x)
{
    int bid = blockIdx.x;
    int tid = threadIdx.x;
    if (bid < NN) {
        int n = bid;
        int o = tid;
        __shared__ float s2[CC];
        float sv = g_s[n * CC + o];
        s2[o] = sv * sv;
        __syncthreads();
        float a0 = 0.f, a1 = 0.f, a2 = 0.f, a3 = 0.f;
#pragma unroll 2
        for (int i = 0; i < CC; i += 4) {
            a0 += s2[i]     * g_ssq[(i)     * OO + o];
            a1 += s2[i + 1] * g_ssq[(i + 1) * OO + o];
            a2 += s2[i + 2] * g_ssq[(i + 2) * OO + o];
            a3 += s2[i + 3] * g_ssq[(i + 3) * OO + o];
        }
        float acc = (a0 + a1) + (a2 + a3);
        const float ws2 = 1.0f / 4608.0f;
        const float ws  = 0.014731391274719738f;
        g_dmul[n * OO + o] = ws * rsqrtf(ws2 * acc + 1e-8f);
    } else {
        int t = (bid - NN) * 512 + tid;
        int e = t * 4;
        int c = e & (CC - 1);
        int n = e >> 21;
        float4 v = *(const float4*)(x + e);
        float4 s = *(const float4*)(g_s + n * CC + c);
        __half h0 = __float2half_rn(v.x * s.x);
        __half h1 = __float2half_rn(v.y * s.y);
        __half h2 = __float2half_rn(v.z * s.z);
        __half h3 = __float2half_rn(v.w * s.w);
        uint2 ph;
        ph.x = (uint32_t)__half_as_ushort(h0) | ((uint32_t)__half_as_ushort(h1) << 16);
        ph.y = (uint32_t)__half_as_ushort(h2) | ((uint32_t)__half_as_ushort(h3) << 16);
        *(uint2*)(g_xh + e) = ph;
    }
}

// ---- A halo staging: 264 rows (4x66 spatial, zero-padded), kc=64 ----------------
static __device__ __forceinline__ void load_A(uint32_t dst, int c0,
                                              int n, int h0, int tid)
{
#pragma unroll
    for (int it = 0; it < 2; ++it) {
        int row = tid + it * 256;
        if (row < 264) {
            int rr = row >= 198 ? 3 : (row >= 132 ? 2 : (row >= 66 ? 1 : 0));
            int cc = row - rr * 66;
            int h = h0 + rr - 1;
            int w = cc - 1;
            const bool ok = ((unsigned)h < (unsigned)HH) && ((unsigned)w < (unsigned)WW);
            const unsigned sz = ok ? 16u : 0u;
            const size_t gi = ((size_t)((n * HH + (ok ? h : 0)) * WW + (ok ? w : 0)) * CC + c0) * 2;
            const char* src = (const char*)g_xh + gi;
            const int r7 = row & 7;
            const uint32_t rbase = dst + (uint32_t)row * 128u;
#pragma unroll
            for (int c = 0; c < 8; ++c)
                CP16(rbase + ((c ^ r7) << 4), src + c * 16, sz);
        }
    }
}

// ---- B staging: one tap = 128 o-rows x kc=64 = 16KB ------------------------------
static __device__ __forceinline__ void load_B(uint32_t dst, int tap, int c0,
                                              int o0, int tid)
{
    const int r  = tid >> 1;
    const int cb = (tid & 1) * 4;
    const int r7 = r & 7;
    const size_t bidx = ((size_t)((tap * OO + o0 + r) * CC) + c0 + cb * 8) * 2;
    const char* src = (const char*)g_wt + bidx;
    const uint32_t rbase = dst + (uint32_t)r * 128u;
#pragma unroll
    for (int c = 0; c < 4; ++c)
        CP16(rbase + (((cb + c) ^ r7) << 4), src + c * 16, 16u);
}

// ---- main conv: tap-pair intervals, R11 skeleton ----------------------------------
__global__ __launch_bounds__(256, 2)
void conv_mma_kernel(const float* __restrict__ bias,
                     const float* __restrict__ nstr,
                     const float* __restrict__ noise,
                     float* __restrict__ out)
{
    extern __shared__ char dynsmem[];
    const uint32_t smbase = smem_u32(dynsmem);

    const int tid  = threadIdx.x;
    const int lane = tid & 31;
    const int wid  = tid >> 5;
    const int wm   = wid & 3;          // M quarter (32 rows)
    const int wn   = wid >> 2;         // N half (64 cols)

    const int o0 = blockIdx.x * 128;
    const int mt = blockIdx.y;
    const int n  = mt >> 5;
    const int h0 = (mt & 31) * 2;

    const int a_row  = wm * 32 + (lane & 15);
    const int a_kh   = lane >> 4;
    const int bg     = lane >> 3;
    const int b_row0 = wn * 64 + ((bg >> 1) << 3) + (lane & 7);
    const int b_kh   = bg & 1;

    const int r0 = a_row, r1 = a_row + 16;
    const int pb0 = (r0 >> 6) * 66 + (r0 & 63);
    const int pb1 = (r1 >> 6) * 66 + (r1 & 63);

    uint32_t bro[4], br7[4];
#pragma unroll
    for (int nb = 0; nb < 4; ++nb) {
        bro[nb] = (uint32_t)(b_row0 + nb * 16) * 128u;
        br7[nb] = (b_row0 + nb * 16) & 7;
    }

    float acc[2][8][4];
#pragma unroll
    for (int mi = 0; mi < 2; ++mi)
#pragma unroll
        for (int ni = 0; ni < 8; ++ni)
#pragma unroll
            for (int q = 0; q < 4; ++q) acc[mi][ni][q] = 0.f;

// one tap's MMAs; TAP compile-time; CURB = current B pair buffer base
#define COMPUTE_TAP(TAP, CURB) do {                                           \
    const int _toff = ((TAP) / 3) * 66 + ((TAP) % 3);                         \
    const uint32_t sbB = (CURB) + (((TAP) & 1) * 16384u);                     \
    const int _p0 = pb0 + _toff, _p1 = pb1 + _toff;                           \
    const uint32_t a0b = smbase + (uint32_t)_p0 * 128u;                       \
    const uint32_t a1b = smbase + (uint32_t)_p1 * 128u;                       \
    const int p07 = _p0 & 7, p17 = _p1 & 7;                                   \
    _Pragma("unroll")                                                         \
    for (int kk = 0; kk < 4; ++kk) {                                          \
        const int rk  = (kk + wid) & 3;                                       \
        const int cha = 2 * rk + a_kh;                                        \
        const int chb = 2 * rk + b_kh;                                        \
        uint32_t aa[2][4], bb[4][4];                                          \
        LDSM4(aa[0], a0b + ((cha ^ p07) << 4));                               \
        LDSM4(aa[1], a1b + ((cha ^ p17) << 4));                               \
        _Pragma("unroll")                                                     \
        for (int nb = 0; nb < 4; ++nb)                                        \
            LDSM4(bb[nb], sbB + bro[nb] + (((unsigned)chb ^ br7[nb]) << 4));  \
        _Pragma("unroll")                                                     \
        for (int mi = 0; mi < 2; ++mi)                                        \
            _Pragma("unroll")                                                 \
            for (int nb = 0; nb < 4; ++nb) {                                  \
                MMA2(acc[mi][2*nb],   aa[mi], bb[nb][0], bb[nb][1]);          \
                MMA2(acc[mi][2*nb+1], aa[mi], bb[nb][2], bb[nb][3]);          \
            }                                                                 \
    }                                                                         \
} while (0)

    const uint32_t sB = smbase + OFF_B0;

    // prologue: A(chunk 0) + B pair (taps 0,1) into buffer 0
    load_A(smbase, 0, n, h0, tid);
    load_B(sB, 0, 0, o0, tid);
    load_B(sB + 16384, 1, 0, o0, tid);
    CP_COMMIT();
    CP_WAIT0();
    __syncthreads();

    int cur = 0;
#pragma unroll 1
    for (int k = 0; k < 8; ++k) {
        const int c0  = k * 64;
        const int c0n = c0 + 64;
        const uint32_t bc0 = sB + (uint32_t)cur * BPAIR;
        const uint32_t bn0 = sB + (uint32_t)(cur ^ 1) * BPAIR;

        // interval 0: compute taps 0,1; prefetch taps 2,3
        load_B(bn0, 2, c0, o0, tid);
        load_B(bn0 + 16384, 3, c0, o0, tid);
        CP_COMMIT();
        COMPUTE_TAP(0, bc0); COMPUTE_TAP(1, bc0);
        CP_WAIT0(); __syncthreads();

        // interval 1: compute taps 2,3; prefetch 4,5
        load_B(bc0, 4, c0, o0, tid);
        load_B(bc0 + 16384, 5, c0, o0, tid);
        CP_COMMIT();
        COMPUTE_TAP(2, bn0); COMPUTE_TAP(3, bn0);
        CP_WAIT0(); __syncthreads();

        // interval 2: compute taps 4,5; prefetch 6,7
        load_B(bn0, 6, c0, o0, tid);
        load_B(bn0 + 16384, 7, c0, o0, tid);
        CP_COMMIT();
        COMPUTE_TAP(4, bc0); COMPUTE_TAP(5, bc0);
        CP_WAIT0(); __syncthreads();

        // interval 3: compute taps 6,7; prefetch tap 8
        load_B(bc0, 8, c0, o0, tid);
        CP_COMMIT();
        COMPUTE_TAP(6, bn0); COMPUTE_TAP(7, bn0);
        CP_WAIT0(); __syncthreads();

        // interval 4: compute tap 8; prefetch next chunk's taps 0,1
        if (k < 7) {
            load_B(bn0, 0, c0n, o0, tid);
            load_B(bn0 + 16384, 1, c0n, o0, tid);
        }
        CP_COMMIT();
        COMPUTE_TAP(8, bc0);
        CP_WAIT0(); __syncthreads();

        // chunk boundary: exposed A reload (single A buffer)
        if (k < 7) {
            load_A(smbase, c0n, n, h0, tid);
            CP_COMMIT();
            CP_WAIT0(); __syncthreads();
        }
        cur ^= 1;   // 5 intervals consumed an odd number of B buffers
    }
#undef COMPUTE_TAP

    // ---- epilogue: demod, noise, bias, leaky_relu * sqrt(2)
    const float nstrv = *nstr;
#pragma unroll
    for (int mi = 0; mi < 2; ++mi) {
#pragma unroll
        for (int half = 0; half < 2; ++half) {
            int m = wm * 32 + mi * 16 + (lane >> 2) + half * 8;
            int h = h0 + (m >> 6);
            int w = m & 63;
            float nz = noise[(n * HH + h) * WW + w] * nstrv;
            size_t base = ((size_t)((n * HH + h) * WW + w)) * OO + o0;
#pragma unroll
            for (int ni = 0; ni < 8; ++ni) {
                int oc = wn * 64 + ni * 8 + 2 * (lane & 3);
                float dm0 = g_dmul[n * OO + o0 + oc];
                float dm1 = g_dmul[n * OO + o0 + oc + 1];
                float b0 = bias[o0 + oc], b1 = bias[o0 + oc + 1];
                float y0 = fmaf(acc[mi][ni][half * 2],     dm0, nz + b0);
                float y1 = fmaf(acc[mi][ni][half * 2 + 1], dm1, nz + b1);
                y0 = (y0 > 0.f ? y0 : 0.2f * y0) * 1.4142135623730951f;
                y1 = (y1 > 0.f ? y1 : 0.2f * y1) * 1.4142135623730951f;
                *(float2*)(out + base + oc) = make_float2(y0, y1);
            }
        }
    }
}

// ---------------------------------------------------------------------------
extern "C" void kernel_launch(void* const* d_in, const int* in_sizes, int n_in,
                              void* d_out, int out_size)
{
    const float* x      = (const float*)d_in[0];
    const float* dlat   = (const float*)d_in[1];
    const float* sw     = (const float*)d_in[2];
    const float* sbv    = (const float*)d_in[3];
    const float* weight = (const float*)d_in[4];
    const float* bias   = (const float*)d_in[5];
    const float* nstr   = (const float*)d_in[6];
    const float* noise  = (const float*)d_in[7];
    const int*   lidx   = (const int*)  d_in[8];
    float* out = (float*)d_out;

    prep_a_kernel<<<NN + CC + 1152, 512>>>(dlat, sw, sbv, lidx, weight);
    prep_b_kernel<<<NN + 16384, 512>>>(x);

    cudaFuncSetAttribute(conv_mma_kernel,
                         cudaFuncAttributeMaxDynamicSharedMemorySize, SMEM_TOTAL);
    conv_mma_kernel<<<dim3(4, 512), 256, SMEM_TOTAL>>>(bias, nstr, noise, out);
}

// round 16
// speedup vs baseline: 1.4422x; 1.0614x over previous
#include <cuda_runtime.h>
#include <cuda_fp16.h>
#include <stdint.h>

// ---------------------------------------------------------------------------
// StyleGAN2 modulated 3x3 conv, NHWC, N=16 H=W=64 C=O=512
// Round 16: consolidation. conv = R11 verbatim (best measured: 857us).
//           prep = R15 (ILP'd style/dmul, fused launches: prep_a | prep_b).
// ---------------------------------------------------------------------------

#define NN 16
#define HH 64
#define WW 64
#define CC 512
#define OO 512
#define NWD 14

#define A_BYTES 33792        // 264 halo rows x 128B  (4x66 spatial, kc=64)
#define OFF_B0  67584        // after 2 A buffers
#define B_BYTES 16384        // 128 o-rows x 128B
#define SMEM_TOTAL (OFF_B0 + 2 * B_BYTES)   // 100352
#define NCHUNK 72            // 9 taps x 8 c-chunks

// ---- device scratch (allocation-free) --------------------------------------
__device__ float g_s[NN * CC];
__device__ float g_dmul[NN * OO];
__device__ float g_ssq[CC * OO];
__device__ __half g_xh[NN * HH * WW * CC];   // fp16(x*s)
__device__ __half g_wt[9 * OO * CC];         // fp16 w^T [tap][o][c]

// ---- helpers -----------------------------------------------------------------
static __device__ __forceinline__ uint32_t smem_u32(const void* p) {
    uint32_t a;
    asm("{ .reg .u64 t; cvta.to.shared.u64 t, %1; cvt.u32.u64 %0, t; }"
        : "=r"(a) : "l"(p));
    return a;
}

#define CP16(dst, src, sz)                                                   \
    asm volatile("cp.async.cg.shared.global [%0], [%1], 16, %2;"             \
                 :: "r"(dst), "l"(src), "r"(sz) : "memory")
#define CP_COMMIT() asm volatile("cp.async.commit_group;" ::: "memory")
#define CP_WAIT0()  asm volatile("cp.async.wait_group 0;" ::: "memory")

#define LDSM4(r, addr)                                                       \
    asm volatile("ldmatrix.sync.aligned.m8n8.x4.shared.b16 "                 \
                 "{%0,%1,%2,%3}, [%4];"                                      \
                 : "=r"((r)[0]), "=r"((r)[1]), "=r"((r)[2]), "=r"((r)[3])    \
                 : "r"(addr))

#define MMA2(d, a, b0, b1)                                                   \
    asm volatile("mma.sync.aligned.m16n8k16.row.col.f32.f16.f16.f32 "        \
                 "{%0,%1,%2,%3}, {%4,%5,%6,%7}, {%8,%9}, {%0,%1,%2,%3};"     \
                 : "+f"((d)[0]), "+f"((d)[1]), "+f"((d)[2]), "+f"((d)[3])    \
                 : "r"((a)[0]), "r"((a)[1]), "r"((a)[2]), "r"((a)[3]),       \
                   "r"(b0), "r"(b1))

// ---- prep_a: style (0..15) | ssq (16..527) | w transpose fp16 (528..1679) -------
__global__ void prep_a_kernel(const float* __restrict__ dlat,
                              const float* __restrict__ sw,
                              const float* __restrict__ sb,
                              const int*   __restrict__ lidx,
                              const float* __restrict__ weight)
{
    int bid = blockIdx.x;
    int tid = threadIdx.x;
    if (bid < NN) {
        int n = bid;
        __shared__ float dl[CC];
        int li = *lidx;
        dl[tid] = dlat[(n * NWD + li) * CC + tid];
        __syncthreads();
        float a0 = 0.f, a1 = 0.f, a2 = 0.f, a3 = 0.f;
#pragma unroll 2
        for (int w = 0; w < CC; w += 4) {
            a0 += dl[w]     * sw[(w)     * CC + tid];
            a1 += dl[w + 1] * sw[(w + 1) * CC + tid];
            a2 += dl[w + 2] * sw[(w + 2) * CC + tid];
            a3 += dl[w + 3] * sw[(w + 3) * CC + tid];
        }
        g_s[n * CC + tid] = ((a0 + a1) + (a2 + a3)) * 0.044194173824159216f + sb[tid];
    } else if (bid < NN + CC) {
        int i = bid - NN;
        float acc = 0.f;
#pragma unroll
        for (int tp = 0; tp < 9; ++tp) {
            float v = weight[(tp * CC + i) * OO + tid];
            acc += v * v;
        }
        g_ssq[i * OO + tid] = acc;
    } else {
        __shared__ float ts[2][32][33];
        int sub = tid >> 8;
        int st  = tid & 255;
        int wb  = (bid - (NN + CC)) * 2 + sub;   // 0..2303
        int tap = wb >> 8;
        int rem = wb & 255;
        int o0 = (rem & 15) * 32;
        int c0 = (rem >> 4) * 32;
        int tx = st & 31, ty = st >> 5;
        for (int j = ty; j < 32; j += 8)
            ts[sub][j][tx] = weight[(tap * CC + c0 + j) * OO + o0 + tx];
        __syncthreads();
        for (int j = ty; j < 32; j += 8) {
            float v = ts[sub][tx][j];
            int oi = (tap * OO + o0 + j) * CC + c0 + tx;
            g_wt[oi] = __float2half_rn(v);
        }
    }
}

// ---- prep_b: dmul (blocks 0..15) | xsplit fp16 (rest) ---------------------------
__global__ void prep_b_kernel(const float* __restrict__ x)
{
    int bid = blockIdx.x;
    int tid = threadIdx.x;
    if (bid < NN) {
        int n = bid;
        int o = tid;
        __shared__ float s2[CC];
        float sv = g_s[n * CC + o];
        s2[o] = sv * sv;
        __syncthreads();
        float a0 = 0.f, a1 = 0.f, a2 = 0.f, a3 = 0.f;
#pragma unroll 2
        for (int i = 0; i < CC; i += 4) {
            a0 += s2[i]     * g_ssq[(i)     * OO + o];
            a1 += s2[i + 1] * g_ssq[(i + 1) * OO + o];
            a2 += s2[i + 2] * g_ssq[(i + 2) * OO + o];
            a3 += s2[i + 3] * g_ssq[(i + 3) * OO + o];
        }
        float acc = (a0 + a1) + (a2 + a3);
        const float ws2 = 1.0f / 4608.0f;
        const float ws  = 0.014731391274719738f;
        g_dmul[n * OO + o] = ws * rsqrtf(ws2 * acc + 1e-8f);
    } else {
        int t = (bid - NN) * 512 + tid;
        int e = t * 4;
        int c = e & (CC - 1);
        int n = e >> 21;
        float4 v = *(const float4*)(x + e);
        float4 s = *(const float4*)(g_s + n * CC + c);
        __half h0 = __float2half_rn(v.x * s.x);
        __half h1 = __float2half_rn(v.y * s.y);
        __half h2 = __float2half_rn(v.z * s.z);
        __half h3 = __float2half_rn(v.w * s.w);
        uint2 ph;
        ph.x = (uint32_t)__half_as_ushort(h0) | ((uint32_t)__half_as_ushort(h1) << 16);
        ph.y = (uint32_t)__half_as_ushort(h2) | ((uint32_t)__half_as_ushort(h3) << 16);
        *(uint2*)(g_xh + e) = ph;
    }
}

// ---- A halo staging: 264 rows (4x66 spatial, zero-padded), kc=64 ----------------
static __device__ __forceinline__ void load_A(uint32_t dst, int c0,
                                              int n, int h0, int tid)
{
#pragma unroll
    for (int it = 0; it < 2; ++it) {
        int row = tid + it * 256;
        if (row < 264) {
            int rr = row >= 198 ? 3 : (row >= 132 ? 2 : (row >= 66 ? 1 : 0));
            int cc = row - rr * 66;
            int h = h0 + rr - 1;
            int w = cc - 1;
            const bool ok = ((unsigned)h < (unsigned)HH) && ((unsigned)w < (unsigned)WW);
            const unsigned sz = ok ? 16u : 0u;
            const size_t gi = ((size_t)((n * HH + (ok ? h : 0)) * WW + (ok ? w : 0)) * CC + c0) * 2;
            const char* src = (const char*)g_xh + gi;
            const int r7 = row & 7;
            const uint32_t rbase = dst + (uint32_t)row * 128u;
#pragma unroll
            for (int c = 0; c < 8; ++c)
                CP16(rbase + ((c ^ r7) << 4), src + c * 16, sz);
        }
    }
}

// ---- B staging: 128 o-rows x kc=64 ------------------------------------------------
static __device__ __forceinline__ void load_B(uint32_t dst, int tap, int c0,
                                               int o0, int tid)
{
    const int r  = tid >> 1;
    const int cb = (tid & 1) * 4;
    const int r7 = r & 7;
    const size_t bidx = ((size_t)((tap * OO + o0 + r) * CC) + c0 + cb * 8) * 2;
    const char* src = (const char*)g_wt + bidx;
    const uint32_t rbase = dst + (uint32_t)r * 128u;
#pragma unroll
    for (int c = 0; c < 4; ++c)
        CP16(rbase + (((cb + c) ^ r7) << 4), src + c * 16, 16u);
}

// ---- main conv on mma.sync (R11 verbatim) ------------------------------------------
__global__ __launch_bounds__(256, 2)
void conv_mma_kernel(const float* __restrict__ bias,
                     const float* __restrict__ nstr,
                     const float* __restrict__ noise,
                     float* __restrict__ out)
{
    extern __shared__ char dynsmem[];
    const uint32_t smbase = smem_u32(dynsmem);

    const int tid  = threadIdx.x;
    const int lane = tid & 31;
    const int wid  = tid >> 5;
    const int wm   = wid & 3;          // M quarter (32 rows)
    const int wn   = wid >> 2;         // N half (64 cols)

    const int o0 = blockIdx.x * 128;
    const int mt = blockIdx.y;
    const int n  = mt >> 5;
    const int h0 = (mt & 31) * 2;

    // ldmatrix lane mappings
    const int a_row  = wm * 32 + (lane & 15);
    const int a_kh   = lane >> 4;
    const int bg     = lane >> 3;
    const int b_row0 = wn * 64 + ((bg >> 1) << 3) + (lane & 7);
    const int b_kh   = bg & 1;

    // A halo per-lane row bases (pb for mi=0,1): p = pb + tapoff
    const int r0 = a_row,      r1 = a_row + 16;
    const int pb0 = (r0 >> 6) * 66 + (r0 & 63);
    const int pb1 = (r1 >> 6) * 66 + (r1 & 63);

    // B fragment row offsets within B buffer
    uint32_t bro[4], br7[4];
#pragma unroll
    for (int nb = 0; nb < 4; ++nb) {
        bro[nb] = (uint32_t)(b_row0 + nb * 16) * 128u;
        br7[nb] = (b_row0 + nb * 16) & 7;
    }

    float acc[2][8][4];
#pragma unroll
    for (int mi = 0; mi < 2; ++mi)
#pragma unroll
        for (int ni = 0; ni < 8; ++ni)
#pragma unroll
            for (int q = 0; q < 4; ++q) acc[mi][ni][q] = 0.f;

    // prologue: A(chunk 0) + B(tap 0, chunk 0)
    load_A(smbase, 0, n, h0, tid);
    load_B(smbase + OFF_B0, 0, 0, o0, tid);
    CP_COMMIT();

    int tap = 0, k = 0, tapoff = 0;
#pragma unroll 1
    for (int i = 0; i < NCHUNK; ++i) {
        CP_WAIT0();          // own copies for chunk i done
        __syncthreads();     // all visible; all finished reading bufs of i-1

        // issue loads for i+1 (B) and, mid-chunk, A for next c-chunk
        if (i + 1 < NCHUNK) {
            int tapj = tap + 1, kj = k;
            if (tapj == 9) { tapj = 0; ++kj; }
            load_B(smbase + OFF_B0 + ((i + 1) & 1) * B_BYTES, tapj, kj * 64, o0, tid);
            if (tap == 3 && k + 1 < 8)
                load_A(smbase + ((k + 1) & 1) * A_BYTES, (k + 1) * 64, n, h0, tid);
        }
        CP_COMMIT();

        const uint32_t sbA = smbase + (k & 1) * A_BYTES;
        const uint32_t sbB = smbase + OFF_B0 + (i & 1) * B_BYTES;
        const int p0 = pb0 + tapoff;
        const int p1 = pb1 + tapoff;
        const uint32_t a0b = sbA + (uint32_t)p0 * 128u;
        const uint32_t a1b = sbA + (uint32_t)p1 * 128u;
        const int p07 = p0 & 7, p17 = p1 & 7;

#pragma unroll
        for (int kk = 0; kk < 4; ++kk) {
            const int rk  = (kk + wid) & 3;          // per-warp phase rotation
            const int cha = 2 * rk + a_kh;
            const int chb = 2 * rk + b_kh;
            uint32_t aa[2][4], bb[4][4];
            LDSM4(aa[0], a0b + ((cha ^ p07) << 4));
            LDSM4(aa[1], a1b + ((cha ^ p17) << 4));
#pragma unroll
            for (int nb = 0; nb < 4; ++nb)
                LDSM4(bb[nb], sbB + bro[nb] + (((unsigned)chb ^ br7[nb]) << 4));
#pragma unroll
            for (int mi = 0; mi < 2; ++mi)
#pragma unroll
                for (int nb = 0; nb < 4; ++nb) {
                    MMA2(acc[mi][2*nb],   aa[mi], bb[nb][0], bb[nb][1]);
                    MMA2(acc[mi][2*nb+1], aa[mi], bb[nb][2], bb[nb][3]);
                }
        }

        if (++tap == 9) { tap = 0; ++k; tapoff = 0; }
        else tapoff += ((tap == 3 || tap == 6) ? 64 : 1);
    }

    // ---- epilogue: demod, noise, bias, leaky_relu * sqrt(2)
    const float nstrv = *nstr;
#pragma unroll
    for (int mi = 0; mi < 2; ++mi) {
#pragma unroll
        for (int half = 0; half < 2; ++half) {
            int m = wm * 32 + mi * 16 + (lane >> 2) + half * 8;
            int h = h0 + (m >> 6);
            int w = m & 63;
            float nz = noise[(n * HH + h) * WW + w] * nstrv;
            size_t base = ((size_t)((n * HH + h) * WW + w)) * OO + o0;
#pragma unroll
            for (int ni = 0; ni < 8; ++ni) {
                int oc = wn * 64 + ni * 8 + 2 * (lane & 3);
                float dm0 = g_dmul[n * OO + o0 + oc];
                float dm1 = g_dmul[n * OO + o0 + oc + 1];
                float b0 = bias[o0 + oc], b1 = bias[o0 + oc + 1];
                float y0 = fmaf(acc[mi][ni][half * 2],     dm0, nz + b0);
                float y1 = fmaf(acc[mi][ni][half * 2 + 1], dm1, nz + b1);
                y0 = (y0 > 0.f ? y0 : 0.2f * y0) * 1.4142135623730951f;
                y1 = (y1 > 0.f ? y1 : 0.2f * y1) * 1.4142135623730951f;
                *(float2*)(out + base + oc) = make_float2(y0, y1);
            }
        }
    }
}

// ---------------------------------------------------------------------------
extern "C" void kernel_launch(void* const* d_in, const int* in_sizes, int n_in,
                              void* d_out, int out_size)
{
    const float* x      = (const float*)d_in[0];
    const float* dlat   = (const float*)d_in[1];
    const float* sw     = (const float*)d_in[2];
    const float* sbv    = (const float*)d_in[3];
    const float* weight = (const float*)d_in[4];
    const float* bias   = (const float*)d_in[5];
    const float* nstr   = (const float*)d_in[6];
    const float* noise  = (const float*)d_in[7];
    const int*   lidx   = (const int*)  d_in[8];
    float* out = (float*)d_out;

    prep_a_kernel<<<NN + CC + 1152, 512>>>(dlat, sw, sbv, lidx, weight);
    prep_b_kernel<<<NN + 16384, 512>>>(x);

    cudaFuncSetAttribute(conv_mma_kernel,
                         cudaFuncAttributeMaxDynamicSharedMemorySize, SMEM_TOTAL);
    conv_mma_kernel<<<dim3(4, 512), 256, SMEM_TOTAL>>>(bias, nstr, noise, out);
}